// round 17
// baseline (speedup 1.0000x reference)
#include <cuda_runtime.h>
#include <cuda_bf16.h>
#include <cuda_fp16.h>
#include <math.h>
#include <stdint.h>

#define BB 2
#define LL 2048
#define DD 256
#define HH 8
#define HD 32
#define BH (BB*HH)
#define QT 32
#define PH 1036        // P strip pitch in u32 (half2 pairs)

// ---------------- scratch (device globals; no allocation allowed) ----------
__device__ float         g_V  [(size_t)BH*LL*HD];
__device__ float         g_O  [(size_t)BH*LL*HD];
__device__ __nv_bfloat16 g_Q16[(size_t)BH*LL*64];    // rows [Qhi d0..31 | Qlo d0..31] (scaled)
__device__ __nv_bfloat16 g_K16[(size_t)BH*LL*64];    // rows [Khi | Klo]
__device__ __half        g_VT16[(size_t)BH*32*LL];   // [bh][d][l]  (single f16)
__device__ float         g_E  [HH*LL];
__device__ float         g_rs [HH*LL];
__device__ float         g_dpart[(size_t)BB*HH*64*LL];
__device__ float         g_dpart2[16*BB*LL];

// ---------------- helpers ----------------------------------------------------
__device__ __forceinline__ uint32_t smem_u32(const void* p){
    uint32_t a;
    asm("{ .reg .u64 t; cvta.to.shared.u64 t, %1; cvt.u32.u64 %0, t; }" : "=r"(a) : "l"(p));
    return a;
}
__device__ __forceinline__ void mma_bf16(float* c, const uint32_t* a,
                                         uint32_t b0, uint32_t b1){
    asm volatile(
        "mma.sync.aligned.m16n8k16.row.col.f32.bf16.bf16.f32 "
        "{%0,%1,%2,%3}, {%4,%5,%6,%7}, {%8,%9}, {%0,%1,%2,%3};"
        : "+f"(c[0]), "+f"(c[1]), "+f"(c[2]), "+f"(c[3])
        : "r"(a[0]), "r"(a[1]), "r"(a[2]), "r"(a[3]), "r"(b0), "r"(b1));
}
__device__ __forceinline__ void mma_f16(float* c, const uint32_t* a,
                                        uint32_t b0, uint32_t b1){
    asm volatile(
        "mma.sync.aligned.m16n8k16.row.col.f32.f16.f16.f32 "
        "{%0,%1,%2,%3}, {%4,%5,%6,%7}, {%8,%9}, {%0,%1,%2,%3};"
        : "+f"(c[0]), "+f"(c[1]), "+f"(c[2]), "+f"(c[3])
        : "r"(a[0]), "r"(a[1]), "r"(a[2]), "r"(a[3]), "r"(b0), "r"(b1));
}
__device__ __forceinline__ void ldmx4(uint32_t* r, uint32_t addr){
    asm volatile("ldmatrix.sync.aligned.m8n8.x4.shared.b16 {%0,%1,%2,%3}, [%4];"
        : "=r"(r[0]),"=r"(r[1]),"=r"(r[2]),"=r"(r[3]) : "r"(addr));
}
__device__ __forceinline__ void ldmx2(uint32_t* r, uint32_t addr){
    asm volatile("ldmatrix.sync.aligned.m8n8.x2.shared.b16 {%0,%1}, [%2];"
        : "=r"(r[0]),"=r"(r[1]) : "r"(addr));
}

// ---------------- kernel 1: QKV projection via mma (bf16 3-product split) ----
#define LK_XL (128*33)
#define LK_WH (2*128*33)
#define LK_WL (2*128*33 + 64*33)
#define LK_TOT (2*128*33 + 2*64*33)

__global__ __launch_bounds__(256) void qkv_mma_kernel(
    const float* __restrict__ x,
    const float* __restrict__ Wq, const float* __restrict__ bq,
    const float* __restrict__ Wk, const float* __restrict__ bk,
    const float* __restrict__ Wv, const float* __restrict__ bv)
{
    extern __shared__ uint32_t usm[];
    uint32_t* Xh = usm;
    uint32_t* Xl = usm + LK_XL;
    uint32_t* Wh = usm + LK_WH;
    uint32_t* Wl = usm + LK_WL;

    const float* Wm; const float* bm;
    if (blockIdx.z == 0)      { Wm=Wq; bm=bq; }
    else if (blockIdx.z == 1) { Wm=Wk; bm=bk; }
    else                      { Wm=Wv; bm=bv; }

    const int m0 = blockIdx.y*128, n0 = blockIdx.x*64;
    const int tid = threadIdx.x, wid = tid>>5, lane = tid&31;
    const int gr = lane>>2, kp = lane&3;

    float c[8][4] = {};
    for (int kc = 0; kc < 4; kc++) {
        __syncthreads();
        #pragma unroll
        for (int j = 0; j < 16; j++) {
            int u2 = tid + j*256;
            int r = u2 >> 5, cc = u2 & 31;
            float2 v = *(const float2*)&x[(size_t)(m0+r)*DD + kc*64 + cc*2];
            __nv_bfloat162 hb = __floats2bfloat162_rn(v.x, v.y);
            __nv_bfloat162 lb = __floats2bfloat162_rn(
                v.x - __bfloat162float(hb.x), v.y - __bfloat162float(hb.y));
            Xh[r*33 + cc] = *(const uint32_t*)&hb;
            Xl[r*33 + cc] = *(const uint32_t*)&lb;
        }
        #pragma unroll
        for (int j = 0; j < 8; j++) {
            int u2 = tid + j*256;
            int r = u2 >> 5, cc = u2 & 31;
            float2 v = *(const float2*)&Wm[(size_t)(n0+r)*DD + kc*64 + cc*2];
            __nv_bfloat162 hb = __floats2bfloat162_rn(v.x, v.y);
            __nv_bfloat162 lb = __floats2bfloat162_rn(
                v.x - __bfloat162float(hb.x), v.y - __bfloat162float(hb.y));
            Wh[r*33 + cc] = *(const uint32_t*)&hb;
            Wl[r*33 + cc] = *(const uint32_t*)&lb;
        }
        __syncthreads();
        #pragma unroll
        for (int s = 0; s < 4; s++) {
            const int mb = wid*16;
            uint32_t ah[4], al[4];
            ah[0] = Xh[(mb+gr  )*33 + s*8 + kp];
            ah[1] = Xh[(mb+gr+8)*33 + s*8 + kp];
            ah[2] = Xh[(mb+gr  )*33 + s*8 + kp + 4];
            ah[3] = Xh[(mb+gr+8)*33 + s*8 + kp + 4];
            al[0] = Xl[(mb+gr  )*33 + s*8 + kp];
            al[1] = Xl[(mb+gr+8)*33 + s*8 + kp];
            al[2] = Xl[(mb+gr  )*33 + s*8 + kp + 4];
            al[3] = Xl[(mb+gr+8)*33 + s*8 + kp + 4];
            #pragma unroll
            for (int nt = 0; nt < 8; nt++) {
                uint32_t bh0 = Wh[(nt*8+gr)*33 + s*8 + kp];
                uint32_t bh1 = Wh[(nt*8+gr)*33 + s*8 + kp + 4];
                uint32_t bl0 = Wl[(nt*8+gr)*33 + s*8 + kp];
                uint32_t bl1 = Wl[(nt*8+gr)*33 + s*8 + kp + 4];
                mma_bf16(c[nt], ah, bh0, bh1);
                mma_bf16(c[nt], ah, bl0, bl1);
                mma_bf16(c[nt], al, bh0, bh1);
            }
        }
    }
    const float SCALE = 0.17677669529663687f;
    #pragma unroll
    for (int nt = 0; nt < 8; nt++) {
        #pragma unroll
        for (int hf = 0; hf < 2; hf++) {
            int m = m0 + wid*16 + gr + hf*8;
            int b = m >> 11, l = m & (LL-1);
            #pragma unroll
            for (int e = 0; e < 2; e++) {
                int n = n0 + nt*8 + kp*2 + e;
                float v = c[nt][hf*2 + e] + bm[n];
                int h = n >> 5, d = n & 31;
                size_t row = (size_t)(b*HH + h)*LL + l;
                if (blockIdx.z == 0) {
                    float sv = v * SCALE;
                    __nv_bfloat16 hi = __float2bfloat16(sv);
                    g_Q16[row*64 + d]      = hi;
                    g_Q16[row*64 + 32 + d] = __float2bfloat16(sv - __bfloat162float(hi));
                } else if (blockIdx.z == 1) {
                    __nv_bfloat16 hi = __float2bfloat16(v);
                    g_K16[row*64 + d]      = hi;
                    g_K16[row*64 + 32 + d] = __float2bfloat16(v - __bfloat162float(hi));
                } else {
                    g_V[row*HD + d] = v;
                }
            }
        }
    }
}

// ---------------- kernel 1b: V transpose -> f16 (single) ---------------------
__global__ __launch_bounds__(256) void vt_kernel()
{
    __shared__ float Vsm[128][33];
    const int bh = blockIdx.x, l0 = blockIdx.y*128;
    const int tid = threadIdx.x;
    for (int idx = tid; idx < 128*32; idx += 256) {
        int i = idx >> 5, d = idx & 31;
        Vsm[i][d] = g_V[((size_t)bh*LL + l0 + i)*HD + d];
    }
    __syncthreads();
    for (int idx = tid; idx < 32*128; idx += 256) {
        int d = idx >> 7, i = idx & 127;
        g_VT16[((size_t)bh*32 + d)*LL + l0 + i] = __float2half_rn(Vsm[i][d]);
    }
}

// ---------------- kernel 2: prior tables via prefix sum ----------------------
__global__ __launch_bounds__(256) void prior_kernel(const float* __restrict__ u)
{
    __shared__ float Es[LL];
    __shared__ float Ps[LL];
    __shared__ float part[256];
    const int h = blockIdx.x, tid = threadIdx.x;
    float uv = u[h];
    float cc = 0.5f / (uv*uv + 1e-6f);
    #pragma unroll
    for (int j = 0; j < 8; j++) {
        int d = tid + j*256;
        float fd = (float)d;
        float e = expf(-(fd*fd)*cc);
        Es[d] = e;
        g_E[h*LL + d] = e;
    }
    __syncthreads();
    float s = 0.f;
    #pragma unroll
    for (int i = 0; i < 8; i++) s += Es[tid*8 + i];
    part[tid] = s;
    __syncthreads();
    if (tid == 0) {
        float run = 0.f;
        for (int i = 0; i < 256; i++) { run += part[i]; part[i] = run; }
    }
    __syncthreads();
    float run = (tid == 0) ? 0.f : part[tid-1];
    #pragma unroll
    for (int i = 0; i < 8; i++) {
        run += Es[tid*8 + i];
        Ps[tid*8 + i] = run;
    }
    __syncthreads();
    float e0 = Es[0];
    #pragma unroll
    for (int j = 0; j < 8; j++) {
        int q = tid + j*256;
        g_rs[h*LL + q] = Ps[q] + Ps[LL-1-q] - e0;
    }
}

// ---------------- kernel 3: FUSED flash-style, QT=32, register-forwarded P ---
// SMEM (u32 units):
//  P strip  [0, 33152)        32 rows x PH (e as half2 pairs)
//  Kst      [33152, 43392)    K chunk 256 keys (hi 5120 | lo 5120)
//  Vst      [43392, 47616)    V chunk 32d x 132
//  Es       [47616, 49664)
//  Qst      [49664, 50720)    32 x 33
//  red      [50720, 51232)    32 warps x 16 rows
//  inv      [51232, 51264)
//  irs      [51264, 51296)
//  Op overlay (epilogue): base SMF_KST, 16 copies x 32q x pitch34 = 17408 u32
#define SMF_P    0
#define SMF_KST  33152
#define SMF_VST  43392
#define SMF_ES   47616
#define SMF_QST  49664
#define SMF_RED  50720
#define SMF_INV  51232
#define SMF_IRS  51264
#define SMF_TOT  51296
#define SMF_BYTES (SMF_TOT*4)

__global__ __launch_bounds__(1024,1) void attn_fused_kernel()
{
    extern __shared__ uint32_t usm2[];
    uint32_t* PU  = usm2 + SMF_P;
    uint32_t* Kst = usm2 + SMF_KST;
    uint32_t* Vst = usm2 + SMF_VST;
    float*    Es  = (float*)(usm2 + SMF_ES);
    uint32_t* Qst = usm2 + SMF_QST;
    float*    red = (float*)(usm2 + SMF_RED);
    float*    inv = (float*)(usm2 + SMF_INV);
    float*    irs = (float*)(usm2 + SMF_IRS);

    const uint32_t sb   = smem_u32(usm2);
    const uint32_t sbK  = sb + SMF_KST*4;
    const uint32_t sbV  = sb + SMF_VST*4;

    const int tid = threadIdx.x, wid = tid >> 5, lane = tid & 31;
    const int gr = lane >> 2, kp = lane & 3;
    const int qt = blockIdx.x, bh = blockIdx.y;
    const int b = bh >> 3, h = bh & 7, q0 = qt * QT;
    const int mt = wid >> 4, ntile = wid & 15;
    const int bl8 = lane & 15;
    const int bkof = ((bl8 >> 3) & 1)*16;

    // ---- phase 0 -------------------------------------------------------------
    {
        int r = tid >> 5, c = tid & 31;
        Qst[r*33 + c] = ((const uint32_t*)g_Q16)[((size_t)bh*LL + q0 + r)*32 + c];
    }
    #pragma unroll
    for (int j = 0; j < 2; j++) { int i = tid + j*1024; Es[i] = g_E[h*LL + i]; }
    if (tid < QT) irs[tid] = 1.0f / (g_rs[h*LL + q0 + tid] + 1e-6f);
    __syncthreads();

    uint32_t qa[2][2][4];
    #pragma unroll
    for (int p = 0; p < 2; p++){
        int base = p*16;
        #pragma unroll
        for (int s = 0; s < 2; s++){
            qa[p][s][0] = Qst[(mt*16 + gr    )*33 + base + kp     + 8*s];
            qa[p][s][1] = Qst[(mt*16 + gr + 8)*33 + base + kp     + 8*s];
            qa[p][s][2] = Qst[(mt*16 + gr    )*33 + base + kp + 4 + 8*s];
            qa[p][s][3] = Qst[(mt*16 + gr + 8)*33 + base + kp + 4 + 8*s];
        }
    }

    // ---- phase 1: scores->e(f16)->PV accumulate; 8 chunks of 256 keys --------
    float s0 = 0.f, s1 = 0.f;
    float co[4][4] = {};
    {
        const uint4* Gk4 = (const uint4*)g_K16;
        const uint4* Gv4 = (const uint4*)g_VT16;
        const size_t kbase = (size_t)bh*LL*8;
        const int g0 = tid, g1 = tid + 1024;
        const int dst0 = (g0>>3)*20 + (g0&3)*4 + ((g0>>2)&1)*5120;
        const int dst1 = (g1>>3)*20 + (g1&3)*4 + ((g1>>2)&1)*5120;
        const int vd = tid >> 5, vp4 = tid & 31;
        const size_t vrow = (size_t)bh*32 + vd;
        const int dstv = vd*132 + vp4*4;
        uint4 pk0 = Gk4[kbase + g0];
        uint4 pk1 = Gk4[kbase + g1];
        uint4 pv  = Gv4[vrow*256 + vp4];

        for (int kc = 0; kc < 8; kc++) {
            __syncthreads();                 // previous chunk compute done
            *(uint4*)(Kst + dst0) = pk0;
            *(uint4*)(Kst + dst1) = pk1;
            *(uint4*)(Vst + dstv) = pv;
            __syncthreads();
            if (kc < 7) {
                pk0 = Gk4[kbase + (kc+1)*2048 + g0];
                pk1 = Gk4[kbase + (kc+1)*2048 + g1];
                pv  = Gv4[vrow*256 + (kc+1)*32 + vp4];
            }
            uint32_t af[4];
            #pragma unroll
            for (int t = 0; t < 2; t++) {
                uint32_t kaddr = sbK + (uint32_t)(ntile*16 + t*8 + (lane&7))*80
                               + (uint32_t)((lane>>3)&3)*16;
                uint32_t bfh[4], bfl[4];
                ldmx4(bfh, kaddr);
                ldmx4(bfl, kaddr + 5120*4);
                float ct[4] = {0.f,0.f,0.f,0.f};
                mma_bf16(ct, qa[0][0], bfh[0], bfh[1]);
                mma_bf16(ct, qa[0][1], bfh[2], bfh[3]);
                mma_bf16(ct, qa[1][0], bfh[0], bfh[1]);
                mma_bf16(ct, qa[1][1], bfh[2], bfh[3]);
                mma_bf16(ct, qa[0][0], bfl[0], bfl[1]);
                mma_bf16(ct, qa[0][1], bfl[2], bfl[3]);
                float e0 = __expf(ct[0]), e1 = __expf(ct[1]);
                float e2 = __expf(ct[2]), e3 = __expf(ct[3]);
                s0 += e0 + e1;
                s1 += e2 + e3;
                __half2 h01 = __floats2half2_rn(e0, e1);
                __half2 h23 = __floats2half2_rn(e2, e3);
                af[t*2]   = *(const uint32_t*)&h01;
                af[t*2+1] = *(const uint32_t*)&h23;
                int colu = kc*128 + ntile*8 + t*4 + kp;
                PU[(mt*16 + gr    )*PH + colu] = af[t*2];
                PU[(mt*16 + gr + 8)*PH + colu] = af[t*2+1];
            }
            // PV: A = this warp's 16q x 16k e-frags (registers), B = V slice
            #pragma unroll
            for (int dt = 0; dt < 4; dt++) {
                uint32_t vaddr = sbV + (uint32_t)(dt*8 + (bl8&7))*528
                               + (uint32_t)ntile*32 + bkof;
                uint32_t bf2[2];
                ldmx2(bf2, vaddr);
                mma_f16(co[dt], af, bf2[0], bf2[1]);
            }
        }
    }
    // row-sum reduction (across kp lanes, then across the 16 n-tiles)
    s0 += __shfl_xor_sync(0xffffffffu, s0, 1);
    s0 += __shfl_xor_sync(0xffffffffu, s0, 2);
    s1 += __shfl_xor_sync(0xffffffffu, s1, 1);
    s1 += __shfl_xor_sync(0xffffffffu, s1, 2);
    if (kp == 0) {
        red[wid*16 + gr]     = s0;
        red[wid*16 + gr + 8] = s1;
    }
    __syncthreads();
    if (tid < QT) {
        int mtr = tid >> 4, rr = tid & 15;
        float s = 0.f;
        #pragma unroll
        for (int nt = 0; nt < 16; nt++) s += red[(mtr*16 + nt)*16 + rr];
        inv[tid] = 1.0f / s;
    }
    __syncthreads();

    // ---- phase 2: discrepancy partials (e*inv, half2 reads) -------------------
    {
        size_t pbase = (((size_t)(b*HH + h))*64 + qt) * LL;
        int k2 = tid;
        int k  = k2*2;
        float2 acc = make_float2(0.f, 0.f);
        #pragma unroll
        for (int q = 0; q < QT; q++) {
            uint32_t pa = PU[q*PH + k2];
            __half2 h2 = *(const __half2*)&pa;
            float2 af = __half22float2(h2);
            float ivq = inv[q];
            float pr0 = Es[abs(q0 + q - k)]     * irs[q];
            float pr1 = Es[abs(q0 + q - k - 1)] * irs[q];
            acc.x += fabsf(af.x*ivq - pr0);
            acc.y += fabsf(af.y*ivq - pr1);
        }
        *(float2*)&g_dpart[pbase + k] = acc;
    }
    __syncthreads();      // disc done (Es dead) -> Op overlay over Kst/Vst/Es/Qst

    // ---- phase 3: O reduction across ntile warps ------------------------------
    {
        float* Op = (float*)Kst;          // 16 copies x 32 q x pitch 34
        #pragma unroll
        for (int dt = 0; dt < 4; dt++) {
            int dcol = dt*8 + kp*2;
            *(float2*)&Op[ntile*1088 + (mt*16 + gr    )*34 + dcol] =
                make_float2(co[dt][0], co[dt][1]);
            *(float2*)&Op[ntile*1088 + (mt*16 + gr + 8)*34 + dcol] =
                make_float2(co[dt][2], co[dt][3]);
        }
    }
    __syncthreads();
    {
        const float* Op = (const float*)Kst;
        int q = tid >> 5, d = tid & 31;
        float s = 0.f;
        #pragma unroll
        for (int nt = 0; nt < 16; nt++) s += Op[nt*1088 + q*34 + d];
        g_O[((size_t)bh*LL + q0 + q)*HD + d] = s * inv[q];
    }
}

// ---------------- kernel 4: discrepancy reduce (2-stage) ----------------------
__global__ void disc_reduce1_kernel()
{
    int k = blockIdx.x*256 + threadIdx.x;
    int seg = blockIdx.y;                   // 16 segments of 32 partials (HH*64=512)
    int b = k >> 11, kk = k & (LL-1);
    const float* base = g_dpart + (size_t)b*HH*64*LL + kk;
    float s = 0.f;
    #pragma unroll 8
    for (int p = seg*32; p < seg*32 + 32; p++) s += base[(size_t)p*LL];
    g_dpart2[seg*BB*LL + k] = s;
}
__global__ void disc_reduce2_kernel(float* __restrict__ dout)
{
    int idx = blockIdx.x*256 + threadIdx.x;
    float s = 0.f;
    #pragma unroll
    for (int seg = 0; seg < 16; seg++) s += g_dpart2[seg*BB*LL + idx];
    dout[idx] = s * (1.0f/(HH*(float)LL));
}

// ---------------- kernel 5: out projection via mma ---------------------------
__global__ __launch_bounds__(256) void outproj_mma_kernel(
    const float* __restrict__ Wo, const float* __restrict__ bo,
    float* __restrict__ out)
{
    extern __shared__ uint32_t usm[];
    uint32_t* Xh = usm;
    uint32_t* Xl = usm + LK_XL;
    uint32_t* Wh = usm + LK_WH;
    uint32_t* Wl = usm + LK_WL;

    const int m0 = blockIdx.y*128, n0 = blockIdx.x*64;
    const int tid = threadIdx.x, wid = tid>>5, lane = tid&31;
    const int gr = lane>>2, kp = lane&3;

    float c[8][4] = {};
    for (int kc = 0; kc < 4; kc++) {
        __syncthreads();
        #pragma unroll
        for (int j = 0; j < 16; j++) {
            int u2 = tid + j*256;
            int r = u2 >> 5, cc = u2 & 31;
            int m = m0 + r;
            int b = m >> 11, l = m & (LL-1);
            int k = kc*64 + cc*2;
            int hh = k >> 5, d = k & 31;
            float2 v = *(const float2*)&g_O[(((size_t)(b*HH + hh))*LL + l)*HD + d];
            __nv_bfloat162 hb = __floats2bfloat162_rn(v.x, v.y);
            __nv_bfloat162 lb = __floats2bfloat162_rn(
                v.x - __bfloat162float(hb.x), v.y - __bfloat162float(hb.y));
            Xh[r*33 + cc] = *(const uint32_t*)&hb;
            Xl[r*33 + cc] = *(const uint32_t*)&lb;
        }
        #pragma unroll
        for (int j = 0; j < 8; j++) {
            int u2 = tid + j*256;
            int r = u2 >> 5, cc = u2 & 31;
            float2 v = *(const float2*)&Wo[(size_t)(n0+r)*DD + kc*64 + cc*2];
            __nv_bfloat162 hb = __floats2bfloat162_rn(v.x, v.y);
            __nv_bfloat162 lb = __floats2bfloat162_rn(
                v.x - __bfloat162float(hb.x), v.y - __bfloat162float(hb.y));
            Wh[r*33 + cc] = *(const uint32_t*)&hb;
            Wl[r*33 + cc] = *(const uint32_t*)&lb;
        }
        __syncthreads();
        #pragma unroll
        for (int s = 0; s < 4; s++) {
            const int mb = wid*16;
            uint32_t ah[4], al[4];
            ah[0] = Xh[(mb+gr  )*33 + s*8 + kp];
            ah[1] = Xh[(mb+gr+8)*33 + s*8 + kp];
            ah[2] = Xh[(mb+gr  )*33 + s*8 + kp + 4];
            ah[3] = Xh[(mb+gr+8)*33 + s*8 + kp + 4];
            al[0] = Xl[(mb+gr  )*33 + s*8 + kp];
            al[1] = Xl[(mb+gr+8)*33 + s*8 + kp];
            al[2] = Xl[(mb+gr  )*33 + s*8 + kp + 4];
            al[3] = Xl[(mb+gr+8)*33 + s*8 + kp + 4];
            #pragma unroll
            for (int nt = 0; nt < 8; nt++) {
                uint32_t bh0 = Wh[(nt*8+gr)*33 + s*8 + kp];
                uint32_t bh1 = Wh[(nt*8+gr)*33 + s*8 + kp + 4];
                uint32_t bl0 = Wl[(nt*8+gr)*33 + s*8 + kp];
                uint32_t bl1 = Wl[(nt*8+gr)*33 + s*8 + kp + 4];
                mma_bf16(c[nt], ah, bh0, bh1);
                mma_bf16(c[nt], ah, bl0, bl1);
                mma_bf16(c[nt], al, bh0, bh1);
            }
        }
    }
    #pragma unroll
    for (int nt = 0; nt < 8; nt++) {
        #pragma unroll
        for (int hf = 0; hf < 2; hf++) {
            int m = m0 + wid*16 + gr + hf*8;
            int n = n0 + nt*8 + kp*2;
            float2 o;
            o.x = c[nt][hf*2]     + bo[n];
            o.y = c[nt][hf*2 + 1] + bo[n+1];
            *(float2*)&out[(size_t)m*DD + n] = o;
        }
    }
}

// ---------------- launch --------------------------------------------------------
extern "C" void kernel_launch(void* const* d_in, const int* in_sizes, int n_in,
                              void* d_out, int out_size)
{
    const float* x  = (const float*)d_in[0];
    const float* Wq = (const float*)d_in[1];
    const float* bq = (const float*)d_in[2];
    const float* Wk = (const float*)d_in[3];
    const float* bk = (const float*)d_in[4];
    const float* Wv = (const float*)d_in[5];
    const float* bv = (const float*)d_in[6];
    const float* u  = (const float*)d_in[7];
    const float* Wo = (const float*)d_in[8];
    const float* bo = (const float*)d_in[9];
    float* out = (float*)d_out;

    cudaFuncSetAttribute(attn_fused_kernel,
                         cudaFuncAttributeMaxDynamicSharedMemorySize, SMF_BYTES);
    cudaFuncSetAttribute(qkv_mma_kernel,
                         cudaFuncAttributeMaxDynamicSharedMemorySize, LK_TOT*4);
    cudaFuncSetAttribute(outproj_mma_kernel,
                         cudaFuncAttributeMaxDynamicSharedMemorySize, LK_TOT*4);

    qkv_mma_kernel<<<dim3(DD/64, (BB*LL)/128, 3), 256, LK_TOT*4>>>(
        x, Wq, bq, Wk, bk, Wv, bv);
    vt_kernel<<<dim3(BH, LL/128), 256>>>();
    prior_kernel<<<HH, 256>>>(u);
    attn_fused_kernel<<<dim3(LL/QT, BH), 1024, SMF_BYTES>>>();
    disc_reduce1_kernel<<<dim3((BB*LL)/256, 16), 256>>>();
    disc_reduce2_kernel<<<(BB*LL)/256, 256>>>(out + (size_t)BB*LL*DD);
    outproj_mma_kernel<<<dim3(DD/64, (BB*LL)/128), 256, LK_TOT*4>>>(Wo, bo, out);
}